// round 10
// baseline (speedup 1.0000x reference)
#include <cuda_runtime.h>
#include <cstdint>

// out[row, n] = sum_t u[row, t] * K[n, 1023 - t] = sum_j u_rev[row, j] * K[n, j]
// Skinny GEMM 512x64x1024 fp32 via fma.rn.f32x2.
// Block = 8 rows x 32 n. WARP-PRIVATE pipelines: warp q owns j-slice
// [q*64, q*64+64): it issues its own K cp.async (4 commit groups of 16 j),
// loads+reverses its own u slice, then consumes chunk-by-chunk with
// incremental wait_group + __syncwarp. No block barrier until the tail.

#define T_LEN   1024
#define N_ORD   64
#define RPB     8
#define NPB     32
#define KP      1028         // pitch % 32 == 4 -> conflict-free LDS.128 phases
#define THREADS 512
#define NBLOCKS 128

__device__ __forceinline__ void cp_async16(void* dst, const void* src) {
    unsigned s = (unsigned)__cvta_generic_to_shared(dst);
    asm volatile("cp.async.cg.shared.global [%0], [%1], 16;\n"
                 :: "r"(s), "l"(src) : "memory");
}
__device__ __forceinline__ void cp_commit() {
    asm volatile("cp.async.commit_group;\n" ::: "memory");
}
template <int N>
__device__ __forceinline__ void cp_wait() {
    asm volatile("cp.async.wait_group %0;\n" :: "n"(N) : "memory");
}
// d += a * b, packed 2xf32 (sm_103a only; ptxas never emits from C++)
__device__ __forceinline__ void ffma2(unsigned long long& d,
                                      unsigned long long a,
                                      unsigned long long b) {
    asm("fma.rn.f32x2 %0, %1, %2, %0;" : "+l"(d) : "l"(a), "l"(b));
}

extern __shared__ float smem[];
// layout: u_rev[8*1024] | K[32*KP]  = (8192 + 32896)*4 = 164352 bytes

__global__ void __launch_bounds__(THREADS, 1)
hippo_last_kernel(const float* __restrict__ U,
                  const float* __restrict__ K,
                  float* __restrict__ out)
{
    float* u_s = smem;                    // time-reversed u
    float* k_s = smem + RPB * T_LEN;

    const int tid  = threadIdx.x;
    const int lane = tid & 31;            // = n within block (mainloop role)
    const int q    = tid >> 5;            // 0..15 : warp owns j-slice [q*64, q*64+64)
    const int jb0  = q * 64;

    const int rg = blockIdx.x >> 1;       // row group (8 rows)
    const int h  = blockIdx.x & 1;        // n half
    const float* Ublk = U + (size_t)rg * RPB * T_LEN;
    const float* Kblk = K + (size_t)h * NPB * T_LEN;

    // ---- K: warp-private cp.async, 4 commit groups (16 j-columns each) ----
    #pragma unroll
    for (int c = 0; c < 4; ++c) {
        #pragma unroll
        for (int w = 0; w < 4; ++w) {
            int idx = lane + 32 * w;      // 0..127 within subchunk
            int nn  = idx >> 2;           // K row 0..31
            int v   = idx & 3;            // float4 within 16-float subchunk
            int j   = jb0 + c * 16 + v * 4;
            cp_async16(&k_s[nn * KP + j], &Kblk[nn * T_LEN + j]);
        }
        cp_commit();
    }

    // ---- u: warp-private slice, loaded reversed (overlaps K stream) ----
    #pragma unroll
    for (int w = 0; w < 4; ++w) {
        int idx = lane + 32 * w;          // 0..127
        int r   = idx >> 4;               // row 0..7
        int jv  = idx & 15;               // float4 within 64-float j-slice
        int j   = jb0 + jv * 4;
        float4 a = *(const float4*)&Ublk[r * T_LEN + (T_LEN - 4) - j];
        *(float4*)&u_s[r * T_LEN + j] = make_float4(a.w, a.z, a.y, a.x);
    }
    __syncwarp();                          // u visible across lanes

    // ---- warp-private mainloop: chunk-by-chunk incremental waits ----
    unsigned long long accA[RPB], accB[RPB];
    #pragma unroll
    for (int r = 0; r < RPB; ++r) { accA[r] = 0ull; accB[r] = 0ull; }

    const float* kp = k_s + lane * KP;    // lane = n

    #pragma unroll
    for (int c = 0; c < 4; ++c) {
        if      (c == 0) cp_wait<3>();
        else if (c == 1) cp_wait<2>();
        else if (c == 2) cp_wait<1>();
        else             cp_wait<0>();
        __syncwarp();                      // K chunk c visible across lanes

        #pragma unroll
        for (int it = 0; it < 4; ++it) {
            const int s = jb0 + c * 16 + it * 4;
            ulonglong2 k2 = *(const ulonglong2*)&kp[s];
            #pragma unroll
            for (int r = 0; r < RPB; ++r) {
                ulonglong2 a2 = *(const ulonglong2*)&u_s[r * T_LEN + s];
                ffma2(accA[r], a2.x, k2.x);
                ffma2(accB[r], a2.y, k2.y);
            }
        }
    }

    // ---- fold packed halves ----
    float vr[RPB];
    #pragma unroll
    for (int r = 0; r < RPB; ++r) {
        float2 fa = *(float2*)&accA[r];
        float2 fb = *(float2*)&accB[r];
        vr[r] = (fa.x + fa.y) + (fb.x + fb.y);
    }

    // ---- cross-warp reduction (the only block barriers) ----
    __syncthreads();                       // all mainloop smem reads done
    *(float4*)&u_s[tid * 8]     = make_float4(vr[0], vr[1], vr[2], vr[3]);
    *(float4*)&u_s[tid * 8 + 4] = make_float4(vr[4], vr[5], vr[6], vr[7]);
    __syncthreads();

    if (tid < RPB * NPB) {                 // 256 outputs
        const int r_out = tid >> 5;        // 0..7
        const int n_out = tid & 31;
        float v = 0.f;
        #pragma unroll
        for (int qq = 0; qq < 16; ++qq)
            v += u_s[(qq * 32 + n_out) * 8 + r_out];
        out[(size_t)(rg * RPB + r_out) * N_ORD + h * NPB + n_out] = v;
    }
}

extern "C" void kernel_launch(void* const* d_in, const int* in_sizes, int n_in,
                              void* d_out, int out_size)
{
    (void)in_sizes; (void)n_in; (void)out_size;
    const float* U   = (const float*)d_in[0];  // (4,2,64,1024) f32
    const float* K   = (const float*)d_in[1];  // (64,1024) f32
    float*       out = (float*)d_out;          // (4,2,64,64) f32

    const size_t SMEM = (RPB * T_LEN + NPB * KP) * sizeof(float); // 164352
    cudaFuncSetAttribute(hippo_last_kernel,
                         cudaFuncAttributeMaxDynamicSharedMemorySize, (int)SMEM);

    hippo_last_kernel<<<NBLOCKS, THREADS, SMEM>>>(U, K, out);
}